// round 5
// baseline (speedup 1.0000x reference)
#include <cuda_runtime.h>
#include <cuda_bf16.h>

#define STEPS 16
typedef unsigned long long u64;

// Coefficient tables, layout [s][slice c][j][lane]; pair index = 128c + 4L + j.
// A = (cx, cy, -cy, -cz), B = (cw, -cw, ct, st)
//   where cx=sp*ct, cy=cp*ct, cz=sp*st, cw=cp*st
__device__ float4 g_ceA[STEPS][4][4][32];
__device__ float4 g_ceB[STEPS][4][4][32];
__device__ float4 g_coA[STEPS][4][4][32];
__device__ float4 g_coB[STEPS][4][4][32];
__device__ float2 g_om[1024];   // (cos(omega), sin(omega))

__global__ void eunn_precompute(const float* __restrict__ omega,
                                const float* __restrict__ et,
                                const float* __restrict__ ot,
                                const float* __restrict__ ep,
                                const float* __restrict__ op)
{
    int idx = blockIdx.x * blockDim.x + threadIdx.x;
    if (idx < 8192) {
        int s = idx >> 9, p = idx & 511;
        int c = p >> 7, rem = p & 127, L = rem >> 2, j = rem & 3;
        float st, ct, sp, cp;
        sincosf(et[s * 512 + p], &st, &ct);
        sincosf(ep[s * 512 + p], &sp, &cp);
        float cx = sp * ct, cy = cp * ct, cz = sp * st, cw = cp * st;
        g_ceA[s][c][j][L] = make_float4(cx, cy, -cy, -cz);
        g_ceB[s][c][j][L] = make_float4(cw, -cw, ct, st);
    } else if (idx < 16384) {
        int t = idx - 8192;
        int s = t >> 9, q = t & 511;
        int c = q >> 7, rem = q & 127, L = rem >> 2, j = rem & 3;
        if (q < 511) {           // ot/op row stride is 511!
            float st, ct, sp, cp;
            sincosf(ot[s * 511 + q], &st, &ct);
            sincosf(op[s * 511 + q], &sp, &cp);
            float cx = sp * ct, cy = cp * ct, cz = sp * st, cw = cp * st;
            g_coA[s][c][j][L] = make_float4(cx, cy, -cy, -cz);
            g_coB[s][c][j][L] = make_float4(cw, -cw, ct, st);
        } else {                  // pair q=511 doesn't exist: exact identity
            g_coA[s][c][j][L] = make_float4(1.f, 0.f, 0.f, 0.f);
            g_coB[s][c][j][L] = make_float4(0.f, 0.f, 1.f, 0.f);
        }
    } else if (idx < 17408) {
        int h = idx - 16384;
        float sn, cs;
        sincosf(omega[h], &sn, &cs);
        g_om[h] = make_float2(cs, sn);
    }
}

// ---- packed f32x2 helpers (FFMA2 is PTX-only on sm_103a) ----
__device__ __forceinline__ u64 pk(float lo, float hi) {
    u64 r; asm("mov.b64 %0, {%1, %2};" : "=l"(r) : "f"(lo), "f"(hi)); return r;
}
__device__ __forceinline__ u64 dup(float v) {
    u64 r; asm("mov.b64 %0, {%1, %1};" : "=l"(r) : "f"(v)); return r;
}
__device__ __forceinline__ void upk(u64 v, float& lo, float& hi) {
    asm("mov.b64 {%0, %1}, %2;" : "=f"(lo), "=f"(hi) : "l"(v));
}
__device__ __forceinline__ u64 f2fma(u64 a, u64 b, u64 c) {
    u64 d; asm("fma.rn.f32x2 %0, %1, %2, %3;" : "=l"(d) : "l"(a), "l"(b), "l"(c)); return d;
}
__device__ __forceinline__ u64 f2mul(u64 a, u64 b) {
    u64 d; asm("mul.rn.f32x2 %0, %1, %2;" : "=l"(d) : "l"(a), "l"(b)); return d;
}

// One rotation on packed state (two rows at once):
//   Ar' = Ar*cx - Ai*cy - Br*cz + Bi*cw
//   Ai' = Ar*cy + Ai*cx - Br*cw - Bi*cz
//   Br' = Br*ct + Ar*st ;  Bi' = Bi*ct + Ai*st
#define ROT(Ar, Ai, Br, Bi)                                               \
    do {                                                                  \
        u64 _ar = (Ar), _ai = (Ai), _br = (Br), _bi = (Bi);               \
        (Ar) = f2fma(_ar, Cx, f2fma(_ai, NCy, f2fma(_br, NCz, f2mul(_bi, Cw))));  \
        (Ai) = f2fma(_ar, Cy, f2fma(_ai, Cx,  f2fma(_br, NCw, f2mul(_bi, NCz)))); \
        (Br) = f2fma(_br, Dx, f2mul(_ar, Dy));                            \
        (Bi) = f2fma(_bi, Dx, f2mul(_ai, Dy));                            \
    } while (0)

#define LOADC(tabA, tabB)                                                 \
    float4 _A = tabA[s][c][j][lane];                                      \
    float4 _B = tabB[s][c][j][lane];                                      \
    u64 Cx = dup(_A.x), Cy = dup(_A.y), NCy = dup(_A.z), NCz = dup(_A.w); \
    u64 Cw = dup(_B.x), NCw = dup(_B.y), Dx = dup(_B.z), Dy = dup(_B.w);

// Block = 256 threads = 8 warps = 2 row-groups of 4 warps (slices c=0..3).
// Warp (g,c): lane L owns elements [256c+8L, 256c+8L+8) of 4 rows, packed
// as f32x2 row-pairs rp=0 (rows 0,1) and rp=1 (rows 2,3).
__global__ void __launch_bounds__(256, 2)
eunn_main(const float* __restrict__ x, float* __restrict__ out)
{
    __shared__ u64 edgeA[8][2][2];   // post-even elem0: [warp][rp][re/im]
    __shared__ u64 edgeB[8][2][2];   // updated boundary b: [target warp][rp][re/im]

    int lane = threadIdx.x & 31;
    int wblk = threadIdx.x >> 5;      // 0..7
    int c    = wblk & 3;              // slice
    int g    = wblk >> 2;             // row-group within block
    int bar  = g + 1;                 // named barrier id (128 threads each)
    int row0 = blockIdx.x * 8 + g * 4;
    int ebase = c * 256 + lane * 8;

    u64 xr[2][8], xi[2][8];
#pragma unroll
    for (int rp = 0; rp < 2; rp++) {
        const float4* pa = (const float4*)(x + (size_t)(row0 + 2*rp)     * 2048 + ebase * 2);
        const float4* pb = (const float4*)(x + (size_t)(row0 + 2*rp + 1) * 2048 + ebase * 2);
#pragma unroll
        for (int i = 0; i < 4; i++) {
            float4 va = __ldg(&pa[i]);
            float4 vb = __ldg(&pb[i]);
            xr[rp][2*i]   = pk(va.x, vb.x);  xi[rp][2*i]   = pk(va.y, vb.y);
            xr[rp][2*i+1] = pk(va.z, vb.z);  xi[rp][2*i+1] = pk(va.w, vb.w);
        }
    }

#pragma unroll 1
    for (int s = 0; s < STEPS; s++) {
        // ---------------- even sweep: pairs (2j, 2j+1), lane-internal ----------------
#pragma unroll
        for (int j = 0; j < 4; j++) {
            LOADC(g_ceA, g_ceB);
#pragma unroll
            for (int rp = 0; rp < 2; rp++)
                ROT(xr[rp][2*j], xi[rp][2*j], xr[rp][2*j+1], xi[rp][2*j+1]);
        }

        // publish post-even element 0 for the left-neighbor warp's boundary pair
        if (lane == 0) {
#pragma unroll
            for (int rp = 0; rp < 2; rp++) {
                edgeA[wblk][rp][0] = xr[rp][0];
                edgeA[wblk][rp][1] = xi[rp][0];
            }
        }
        asm volatile("bar.sync %0, 128;" :: "r"(bar) : "memory");

        // neighbor's (post-even) element 0
        u64 n0r[2], n0i[2];
#pragma unroll
        for (int rp = 0; rp < 2; rp++) {
            n0r[rp] = __shfl_down_sync(0xffffffffu, xr[rp][0], 1);
            n0i[rp] = __shfl_down_sync(0xffffffffu, xi[rp][0], 1);
        }
        if (lane == 31 && c < 3) {
#pragma unroll
            for (int rp = 0; rp < 2; rp++) {
                n0r[rp] = edgeA[wblk + 1][rp][0];
                n0i[rp] = edgeA[wblk + 1][rp][1];
            }
        }

        // ---------------- odd sweep ----------------
#pragma unroll
        for (int j = 0; j < 3; j++) {       // internal pairs (2j+1, 2j+2)
            LOADC(g_coA, g_coB);
#pragma unroll
            for (int rp = 0; rp < 2; rp++)
                ROT(xr[rp][2*j+1], xi[rp][2*j+1], xr[rp][2*j+2], xi[rp][2*j+2]);
        }
        {   // boundary pair j=3: a = my element 7, b = neighbor's element 0
            const int j = 3;
            LOADC(g_coA, g_coB);
            u64 nbr[2], nbi[2];
#pragma unroll
            for (int rp = 0; rp < 2; rp++) {
                u64 Ar = xr[rp][7], Ai = xi[rp][7], Br = n0r[rp], Bi = n0i[rp];
                xr[rp][7] = f2fma(Ar, Cx, f2fma(Ai, NCy, f2fma(Br, NCz, f2mul(Bi, Cw))));
                xi[rp][7] = f2fma(Ar, Cy, f2fma(Ai, Cx,  f2fma(Br, NCw, f2mul(Bi, NCz))));
                nbr[rp]   = f2fma(Br, Dx, f2mul(Ar, Dy));
                nbi[rp]   = f2fma(Bi, Dx, f2mul(Ai, Dy));
            }
            if (lane == 31 && c < 3) {      // route updated b to right warp
#pragma unroll
                for (int rp = 0; rp < 2; rp++) {
                    edgeB[wblk + 1][rp][0] = nbr[rp];
                    edgeB[wblk + 1][rp][1] = nbi[rp];
                }
            }
#pragma unroll
            for (int rp = 0; rp < 2; rp++) {
                u64 ur = __shfl_up_sync(0xffffffffu, nbr[rp], 1);
                u64 ui = __shfl_up_sync(0xffffffffu, nbi[rp], 1);
                if (lane > 0) { xr[rp][0] = ur; xi[rp][0] = ui; }
            }
        }
        asm volatile("bar.sync %0, 128;" :: "r"(bar) : "memory");
        if (lane == 0 && c > 0) {
#pragma unroll
            for (int rp = 0; rp < 2; rp++) {
                xr[rp][0] = edgeB[wblk][rp][0];
                xi[rp][0] = edgeB[wblk][rp][1];
            }
        }
    }

    // ---------------- final diagonal phase (packed) + store ----------------
#pragma unroll
    for (int k = 0; k < 8; k++) {
        float2 m = g_om[ebase + k];
        u64 Mx = dup(m.x), My = dup(m.y);
#pragma unroll
        for (int rp = 0; rp < 2; rp++) {
            u64 r = xr[rp][k], i = xi[rp][k];
            // r' = r*mx - i*my ; i' = r*my + i*mx   (use -my via scalar neg in dup)
            u64 NMy = dup(-m.y);
            xr[rp][k] = f2fma(i, NMy, f2mul(r, Mx));
            xi[rp][k] = f2fma(i, Mx,  f2mul(r, My));
            (void)My;
        }
    }
#pragma unroll
    for (int rp = 0; rp < 2; rp++) {
        float4* oa = (float4*)(out + (size_t)(row0 + 2*rp)     * 2048 + ebase * 2);
        float4* ob = (float4*)(out + (size_t)(row0 + 2*rp + 1) * 2048 + ebase * 2);
#pragma unroll
        for (int i = 0; i < 4; i++) {
            float r0a, r0b, i0a, i0b, r1a, r1b, i1a, i1b;
            upk(xr[rp][2*i],   r0a, r0b);  upk(xi[rp][2*i],   i0a, i0b);
            upk(xr[rp][2*i+1], r1a, r1b);  upk(xi[rp][2*i+1], i1a, i1b);
            oa[i] = make_float4(r0a, i0a, r1a, i1a);
            ob[i] = make_float4(r0b, i0b, r1b, i1b);
        }
    }
}

extern "C" void kernel_launch(void* const* d_in, const int* in_sizes, int n_in,
                              void* d_out, int out_size)
{
    const float* x     = (const float*)d_in[0];
    const float* omega = (const float*)d_in[1];
    const float* et    = (const float*)d_in[2];
    const float* ot    = (const float*)d_in[3];
    const float* ep    = (const float*)d_in[4];
    const float* op    = (const float*)d_in[5];

    eunn_precompute<<<68, 256>>>(omega, et, ot, ep, op);   // 17408 threads

    int rows = in_sizes[0] / 2048;                         // 4096
    eunn_main<<<rows / 8, 256>>>(x, (float*)d_out);        // 8 rows per block
}

// round 6
// speedup vs baseline: 1.1246x; 1.1246x over previous
#include <cuda_runtime.h>
#include <cuda_bf16.h>

#define STEPS 16

// ---- coefficient tables ------------------------------------------------
// Slices: warp c (0..7) owns elements [128c, 128c+128) of its rows; lane L
// owns 4 consecutive elements e0..e3 = 128c + 4L + {0..3}.
// Even pairs  p = 64c + 2L + j (j=0: (e0,e1), j=1: (e2,e3)) -- lane-internal.
// Odd  pairs  q = 64c + 2L + j (j=0: (e1,e2) internal, j=1: (e3, next e0)).
//
// gE4/gO4: (cx, cy, cz, cw) = (sp*ct, cp*ct, sp*st, cp*st)   [a'-update]
// gE2[s][c][L] = (ct0, st0, ct1, st1) for pairs j=0, j=1      [b'-updates]
// gO2[s][c][L] = (ct, st of q0=64c+2L | ct, st of q0-1)       [own b'(e2) | left-boundary b'(e0)]
//   q0-1 < 0  -> identity (1,0);  q = 511 doesn't exist -> identity in gO4.
__device__ float4 gE4[STEPS][8][2][32];
__device__ float4 gE2[STEPS][8][32];
__device__ float4 gO4[STEPS][8][2][32];
__device__ float4 gO2[STEPS][8][32];
__device__ float2 g_om[1024];

__global__ void eunn_precompute(const float* __restrict__ omega,
                                const float* __restrict__ et,
                                const float* __restrict__ ot,
                                const float* __restrict__ ep,
                                const float* __restrict__ op)
{
    int idx = blockIdx.x * blockDim.x + threadIdx.x;
    if (idx < 8192) {
        // even pair p
        int s = idx >> 9, p = idx & 511;
        int c = p >> 6, w = p & 63, L = w >> 1, j = w & 1;
        float st, ct, sp, cp;
        sincosf(et[s * 512 + p], &st, &ct);
        sincosf(ep[s * 512 + p], &sp, &cp);
        gE4[s][c][j][L] = make_float4(sp * ct, cp * ct, sp * st, cp * st);
        ((float2*)&gE2[s][c][L])[j] = make_float2(ct, st);
    } else if (idx < 16384) {
        // odd pair q   (ot/op row stride is 511!)
        int t = idx - 8192;
        int s = t >> 9, q = t & 511;
        int c = q >> 6, w = q & 63, L = w >> 1, j = w & 1;
        if (q < 511) {
            float st, ct, sp, cp;
            sincosf(ot[s * 511 + q], &st, &ct);
            sincosf(op[s * 511 + q], &sp, &cp);
            gO4[s][c][j][L] = make_float4(sp * ct, cp * ct, sp * st, cp * st);
            if (j == 0) {
                ((float2*)&gO2[s][c][L])[0] = make_float2(ct, st);
            } else {
                // this pair is the LEFT boundary of pair-owner q+1
                int qn = q + 1;
                int cn = qn >> 6, Ln = (qn & 63) >> 1;
                ((float2*)&gO2[s][cn][Ln])[1] = make_float2(ct, st);
            }
        } else {
            // q == 511: boundary pair beyond row end -> identity a'-update
            gO4[s][7][1][31] = make_float4(1.f, 0.f, 0.f, 0.f);
            // and the q=-1 slot (c=0, L=0): identity b'-update
            ((float2*)&gO2[s][0][0])[1] = make_float2(1.f, 0.f);
        }
    } else if (idx < 17408) {
        int h = idx - 16384;
        float sn, cs;
        sincosf(omega[h], &sn, &cs);
        g_om[h] = make_float2(cs, sn);
    }
}

// full 12-FMA rotation of (A, B) with coefficients (c4; dt, ds)
#define ROT(Ar, Ai, Br, Bi, c4, dt, ds)                                    \
    do {                                                                   \
        float _ar = (Ar), _ai = (Ai), _br = (Br), _bi = (Bi);              \
        (Ar) = _ar * (c4).x - _ai * (c4).y - _br * (c4).z + _bi * (c4).w;  \
        (Ai) = _ar * (c4).y + _ai * (c4).x - _br * (c4).w - _bi * (c4).z;  \
        (Br) = _br * (dt) + _ar * (ds);                                    \
        (Bi) = _bi * (dt) + _ai * (ds);                                    \
    } while (0)

// Block = 256 threads = 8 warps = 8 slices of ONE group of 8 rows.
// Warp c, lane L: elements 128c + 4L + {0..3} of rows row0..row0+7 in regs.
__global__ void __launch_bounds__(256, 2)
eunn_main(const float* __restrict__ x, float* __restrict__ out)
{
    __shared__ float sE0[2][8][8][2];   // [parity][slice][row][re/im]: post-even e0
    __shared__ float sE3[2][8][8][2];   // post-even e3

    int lane  = threadIdx.x & 31;
    int c     = threadIdx.x >> 5;        // slice 0..7
    int row0  = blockIdx.x * 8;
    int ebase = c * 128 + lane * 4;

    float xr[8][4], xi[8][4];
#pragma unroll
    for (int r = 0; r < 8; r++) {
        const float4* p4 = (const float4*)(x + (size_t)(row0 + r) * 2048 + ebase * 2);
        float4 v0 = __ldg(&p4[0]);
        float4 v1 = __ldg(&p4[1]);
        xr[r][0] = v0.x; xi[r][0] = v0.y; xr[r][1] = v0.z; xi[r][1] = v0.w;
        xr[r][2] = v1.x; xi[r][2] = v1.y; xr[r][3] = v1.z; xi[r][3] = v1.w;
    }

#pragma unroll 1
    for (int s = 0; s < STEPS; s++) {
        int par = s & 1;
        // ---------------- even sweep: pairs (e0,e1), (e2,e3) ----------------
        {
            float4 A0 = gE4[s][c][0][lane];
            float4 A1 = gE4[s][c][1][lane];
            float4 T  = gE2[s][c][lane];
#pragma unroll
            for (int r = 0; r < 8; r++) {
                ROT(xr[r][0], xi[r][0], xr[r][1], xi[r][1], A0, T.x, T.y);
                ROT(xr[r][2], xi[r][2], xr[r][3], xi[r][3], A1, T.z, T.w);
            }
        }

        // publish boundary values (post-even) for slice neighbors
        if (lane == 0) {
#pragma unroll
            for (int r = 0; r < 8; r++) {
                sE0[par][c][r][0] = xr[r][0];
                sE0[par][c][r][1] = xi[r][0];
            }
        }
        if (lane == 31) {
#pragma unroll
            for (int r = 0; r < 8; r++) {
                sE3[par][c][r][0] = xr[r][3];
                sE3[par][c][r][1] = xi[r][3];
            }
        }
        __syncthreads();

        // ---------------- odd sweep ----------------
        {
            float4 B0 = gO4[s][c][0][lane];   // internal pair (e1,e2)
            float4 B1 = gO4[s][c][1][lane];   // boundary pair a'-update (e3)
            float4 U  = gO2[s][c][lane];      // (ct,st | ct_left, st_left)
            bool  smR = (lane == 31) && (c < 7);
            bool  smL = (lane == 0)  && (c > 0);
#pragma unroll
            for (int r = 0; r < 8; r++) {
                // gather: right neighbor's post-even e0, left neighbor's post-even e3
                float nbr = __shfl_down_sync(0xffffffffu, xr[r][0], 1);
                float nbi = __shfl_down_sync(0xffffffffu, xi[r][0], 1);
                float lar = __shfl_up_sync  (0xffffffffu, xr[r][3], 1);
                float lai = __shfl_up_sync  (0xffffffffu, xi[r][3], 1);
                if (smR) { nbr = sE0[par][c + 1][r][0]; nbi = sE0[par][c + 1][r][1]; }
                if (smL) { lar = sE3[par][c - 1][r][0]; lai = sE3[par][c - 1][r][1]; }

                // internal pair (e1,e2): full rotation
                ROT(xr[r][1], xi[r][1], xr[r][2], xi[r][2], B0, U.x, U.y);

                // boundary pair: a'-update of e3 (partner = neighbor's e0)
                float ar = xr[r][3], ai = xi[r][3];
                xr[r][3] = ar * B1.x - ai * B1.y - nbr * B1.z + nbi * B1.w;
                xi[r][3] = ar * B1.y + ai * B1.x - nbr * B1.w - nbi * B1.z;

                // left-boundary pair: b'-update of e0 (partner = left's e3)
                xr[r][0] = xr[r][0] * U.z + lar * U.w;
                xi[r][0] = xi[r][0] * U.z + lai * U.w;
            }
        }
    }

    // ---------------- final diagonal phase + store ----------------
    const float4* omv = (const float4*)g_om;          // (cos,sin) pairs
    float4 mA = omv[ebase >> 1];                      // om[ebase+0], om[ebase+1]
    float4 mB = omv[(ebase >> 1) + 1];                // om[ebase+2], om[ebase+3]
#pragma unroll
    for (int r = 0; r < 8; r++) {
        float r0 = xr[r][0] * mA.x - xi[r][0] * mA.y;
        float i0 = xr[r][0] * mA.y + xi[r][0] * mA.x;
        float r1 = xr[r][1] * mA.z - xi[r][1] * mA.w;
        float i1 = xr[r][1] * mA.w + xi[r][1] * mA.z;
        float r2 = xr[r][2] * mB.x - xi[r][2] * mB.y;
        float i2 = xr[r][2] * mB.y + xi[r][2] * mB.x;
        float r3 = xr[r][3] * mB.z - xi[r][3] * mB.w;
        float i3 = xr[r][3] * mB.w + xi[r][3] * mB.z;
        float4* o4 = (float4*)(out + (size_t)(row0 + r) * 2048 + ebase * 2);
        o4[0] = make_float4(r0, i0, r1, i1);
        o4[1] = make_float4(r2, i2, r3, i3);
    }
}

extern "C" void kernel_launch(void* const* d_in, const int* in_sizes, int n_in,
                              void* d_out, int out_size)
{
    const float* x     = (const float*)d_in[0];
    const float* omega = (const float*)d_in[1];
    const float* et    = (const float*)d_in[2];
    const float* ot    = (const float*)d_in[3];
    const float* ep    = (const float*)d_in[4];
    const float* op    = (const float*)d_in[5];

    eunn_precompute<<<68, 256>>>(omega, et, ot, ep, op);   // 17408 threads

    int rows = in_sizes[0] / 2048;                         // 4096
    eunn_main<<<rows / 8, 256>>>(x, (float*)d_out);        // 8 rows per block
}

// round 7
// speedup vs baseline: 1.2561x; 1.1169x over previous
#include <cuda_runtime.h>
#include <cuda_bf16.h>

#define STEPS 16

// ---- coefficient tables -------------------------------------------------
// Warp slice c (0..3) owns elements [256c, 256c+256); lane L owns the 8
// elements e0..e7 = 256c + 8L + {0..7} of its 4 rows.
//
// Even pairs  p = 128c + 4L + j, j=0..3 : (e2j, e2j+1)           lane-internal
// Odd  pairs  q = 128c + 4L + j, j=0..2 : (e2j+1, e2j+2)         lane-internal
//             q = 128c + 4L + 3         : (e7, next-lane e0)     boundary
//             q = 128c + 4L - 1         : (left-lane e7, e0)     boundary
//
// A-tables: (cx, cy, cz, cw) = (sp*ct, cp*ct, sp*st, cp*st)  [a'-update, 8 FMA]
// B-tables: packed (ct, st) per pair                          [b'-update, 4 FMA]
//   gEB[s][c][k][L] = (ct_{j=2k}, st_{j=2k}, ct_{j=2k+1}, st_{j=2k+1})
//   gOB[s][c][0][L] = (ct_q0, st_q0, ct_q1, st_q1)
//   gOB[s][c][1][L] = (ct_q2, st_q2, ct_left, st_left)   left = q = 128c+4L-1
// Nonexistent pairs (q=-1, q=511) -> exact identity.
__device__ float4 gEA[STEPS][4][4][32];
__device__ float4 gEB[STEPS][4][2][32];
__device__ float4 gOA[STEPS][4][4][32];
__device__ float4 gOB[STEPS][4][2][32];
__device__ float2 g_om[1024];

__global__ void eunn_precompute(const float* __restrict__ omega,
                                const float* __restrict__ et,
                                const float* __restrict__ ot,
                                const float* __restrict__ ep,
                                const float* __restrict__ op)
{
    int idx = blockIdx.x * blockDim.x + threadIdx.x;
    if (idx < 8192) {
        // even pair p
        int s = idx >> 9, p = idx & 511;
        int c = p >> 7, w = p & 127, L = w >> 2, j = w & 3;
        float st, ct, sp, cp;
        sincosf(et[s * 512 + p], &st, &ct);
        sincosf(ep[s * 512 + p], &sp, &cp);
        gEA[s][c][j][L] = make_float4(sp * ct, cp * ct, sp * st, cp * st);
        ((float2*)&gEB[s][c][j >> 1][L])[j & 1] = make_float2(ct, st);
    } else if (idx < 16384) {
        // odd pair q   (NB: ot/op row stride is 511)
        int t = idx - 8192;
        int s = t >> 9, q = t & 511;
        if (q < 511) {
            int c = q >> 7, w = q & 127, L = w >> 2, j = w & 3;
            float st, ct, sp, cp;
            sincosf(ot[s * 511 + q], &st, &ct);
            sincosf(op[s * 511 + q], &sp, &cp);
            gOA[s][c][j][L] = make_float4(sp * ct, cp * ct, sp * st, cp * st);
            if (j == 0)      ((float2*)&gOB[s][c][0][L])[0] = make_float2(ct, st);
            else if (j == 1) ((float2*)&gOB[s][c][0][L])[1] = make_float2(ct, st);
            else if (j == 2) ((float2*)&gOB[s][c][1][L])[0] = make_float2(ct, st);
            else {
                // j==3: this is the LEFT boundary pair of the next lane
                int q1 = q + 1;
                int cn = q1 >> 7, Ln = (q1 & 127) >> 2;
                ((float2*)&gOB[s][cn][1][Ln])[1] = make_float2(ct, st);
            }
        } else {
            // q == 511 doesn't exist: identity a'-update for the last lane's
            // boundary pair, and identity left-b'-update for lane (c=0, L=0).
            gOA[s][3][3][31] = make_float4(1.f, 0.f, 0.f, 0.f);
            ((float2*)&gOB[s][0][1][0])[1] = make_float2(1.f, 0.f);
        }
    } else if (idx < 17408) {
        int h = idx - 16384;
        float sn, cs;
        sincosf(omega[h], &sn, &cs);
        g_om[h] = make_float2(cs, sn);
    }
}

// full 12-FMA rotation of pair (A, B)
#define ROT(Ar, Ai, Br, Bi, c4, dt, ds)                                    \
    do {                                                                   \
        float _ar = (Ar), _ai = (Ai), _br = (Br), _bi = (Bi);              \
        (Ar) = _ar * (c4).x - _ai * (c4).y - _br * (c4).z + _bi * (c4).w;  \
        (Ai) = _ar * (c4).y + _ai * (c4).x - _br * (c4).w - _bi * (c4).z;  \
        (Br) = _br * (dt) + _ar * (ds);                                    \
        (Bi) = _bi * (dt) + _ai * (ds);                                    \
    } while (0)

// Block = 256 threads = 2 row-groups (g) x 4 slice-warps (c).
// Warp (g,c), lane L: elements 256c + 8L + {0..7} of rows row0..row0+3.
__global__ void __launch_bounds__(256, 2)
eunn_main(const float* __restrict__ x, float* __restrict__ out)
{
    __shared__ float sE0[2][2][4][4][2];   // [parity][g][slice][row][re/im] post-even e0
    __shared__ float sE7[2][2][4][4][2];   // post-even e7

    int lane  = threadIdx.x & 31;
    int wblk  = threadIdx.x >> 5;
    int c     = wblk & 3;                  // slice
    int g     = wblk >> 2;                 // row-group
    int row0  = blockIdx.x * 8 + g * 4;
    int ebase = c * 256 + lane * 8;

    float xr[4][8], xi[4][8];
#pragma unroll
    for (int r = 0; r < 4; r++) {
        const float4* p4 = (const float4*)(x + (size_t)(row0 + r) * 2048 + ebase * 2);
#pragma unroll
        for (int i = 0; i < 4; i++) {
            float4 v = __ldg(&p4[i]);
            xr[r][2*i] = v.x; xi[r][2*i] = v.y; xr[r][2*i+1] = v.z; xi[r][2*i+1] = v.w;
        }
    }

#pragma unroll 1
    for (int s = 0; s < STEPS; s++) {
        int par = s & 1;
        // prefetch ALL coefficients for this step (12 independent LDG.128)
        float4 EA0 = gEA[s][c][0][lane], EA1 = gEA[s][c][1][lane];
        float4 EA2 = gEA[s][c][2][lane], EA3 = gEA[s][c][3][lane];
        float4 EB0 = gEB[s][c][0][lane], EB1 = gEB[s][c][1][lane];
        float4 OA0 = gOA[s][c][0][lane], OA1 = gOA[s][c][1][lane];
        float4 OA2 = gOA[s][c][2][lane], OA3 = gOA[s][c][3][lane];
        float4 OB0 = gOB[s][c][0][lane], OB1 = gOB[s][c][1][lane];

        // ---------------- even sweep: 4 lane-internal pairs ----------------
#pragma unroll
        for (int r = 0; r < 4; r++) {
            ROT(xr[r][0], xi[r][0], xr[r][1], xi[r][1], EA0, EB0.x, EB0.y);
            ROT(xr[r][2], xi[r][2], xr[r][3], xi[r][3], EA1, EB0.z, EB0.w);
            ROT(xr[r][4], xi[r][4], xr[r][5], xi[r][5], EA2, EB1.x, EB1.y);
            ROT(xr[r][6], xi[r][6], xr[r][7], xi[r][7], EA3, EB1.z, EB1.w);
        }

        // publish slice-boundary values (post-even) for neighbor warps
        if (lane == 0) {
#pragma unroll
            for (int r = 0; r < 4; r++) {
                sE0[par][g][c][r][0] = xr[r][0];
                sE0[par][g][c][r][1] = xi[r][0];
            }
        }
        if (lane == 31) {
#pragma unroll
            for (int r = 0; r < 4; r++) {
                sE7[par][g][c][r][0] = xr[r][7];
                sE7[par][g][c][r][1] = xi[r][7];
            }
        }
        asm volatile("bar.sync %0, 128;" :: "r"(g + 1) : "memory");

        // batched neighbor gather (pre-odd values): right e0, left e7
        float nbr[4], nbi[4], lar[4], lai[4];
#pragma unroll
        for (int r = 0; r < 4; r++) {
            nbr[r] = __shfl_down_sync(0xffffffffu, xr[r][0], 1);
            nbi[r] = __shfl_down_sync(0xffffffffu, xi[r][0], 1);
            lar[r] = __shfl_up_sync  (0xffffffffu, xr[r][7], 1);
            lai[r] = __shfl_up_sync  (0xffffffffu, xi[r][7], 1);
        }
        if (lane == 31 && c < 3) {
#pragma unroll
            for (int r = 0; r < 4; r++) {
                nbr[r] = sE0[par][g][c + 1][r][0];
                nbi[r] = sE0[par][g][c + 1][r][1];
            }
        }
        if (lane == 0 && c > 0) {
#pragma unroll
            for (int r = 0; r < 4; r++) {
                lar[r] = sE7[par][g][c - 1][r][0];
                lai[r] = sE7[par][g][c - 1][r][1];
            }
        }

        // ---------------- odd sweep (all pairs disjoint) ----------------
#pragma unroll
        for (int r = 0; r < 4; r++) {
            // internal pairs (e1,e2), (e3,e4), (e5,e6)
            ROT(xr[r][1], xi[r][1], xr[r][2], xi[r][2], OA0, OB0.x, OB0.y);
            ROT(xr[r][3], xi[r][3], xr[r][4], xi[r][4], OA1, OB0.z, OB0.w);
            ROT(xr[r][5], xi[r][5], xr[r][6], xi[r][6], OA2, OB1.x, OB1.y);
            // boundary pair a'-half: e7 with right neighbor's pre-odd e0
            float ar = xr[r][7], ai = xi[r][7];
            xr[r][7] = ar * OA3.x - ai * OA3.y - nbr[r] * OA3.z + nbi[r] * OA3.w;
            xi[r][7] = ar * OA3.y + ai * OA3.x - nbr[r] * OA3.w - nbi[r] * OA3.z;
            // left-boundary pair b'-half: e0 with left neighbor's pre-odd e7
            xr[r][0] = xr[r][0] * OB1.z + lar[r] * OB1.w;
            xi[r][0] = xi[r][0] * OB1.z + lai[r] * OB1.w;
        }
    }

    // ---------------- final diagonal phase + store ----------------
    const float4* omv = (const float4*)g_om;
#pragma unroll
    for (int r = 0; r < 4; r++) {
        float4* o4 = (float4*)(out + (size_t)(row0 + r) * 2048 + ebase * 2);
#pragma unroll
        for (int i = 0; i < 4; i++) {
            float4 m = omv[(ebase >> 1) + i];   // om[ebase+2i], om[ebase+2i+1]
            float r0 = xr[r][2*i]   * m.x - xi[r][2*i]   * m.y;
            float i0 = xr[r][2*i]   * m.y + xi[r][2*i]   * m.x;
            float r1 = xr[r][2*i+1] * m.z - xi[r][2*i+1] * m.w;
            float i1 = xr[r][2*i+1] * m.w + xi[r][2*i+1] * m.z;
            o4[i] = make_float4(r0, i0, r1, i1);
        }
    }
}

extern "C" void kernel_launch(void* const* d_in, const int* in_sizes, int n_in,
                              void* d_out, int out_size)
{
    const float* x     = (const float*)d_in[0];
    const float* omega = (const float*)d_in[1];
    const float* et    = (const float*)d_in[2];
    const float* ot    = (const float*)d_in[3];
    const float* ep    = (const float*)d_in[4];
    const float* op    = (const float*)d_in[5];

    eunn_precompute<<<68, 256>>>(omega, et, ot, ep, op);   // 17408 threads

    int rows = in_sizes[0] / 2048;                         // 4096
    eunn_main<<<rows / 8, 256>>>(x, (float*)d_out);        // 8 rows per block
}